// round 7
// baseline (speedup 1.0000x reference)
#include <cuda_runtime.h>

// lp[r,p] = sum_f w[p,f]^2 * sum_e x[r,f,e]^2
// x: [R=32768, F=64, E=16] fp32 (row = 1024 floats = 4KB contiguous)
// w: [P=10, F=64] fp32 ; out: [R, 10] fp32
//
// Warp-per-row, software-pipelined across grid-stride iterations so a load
// batch is ALWAYS in flight (kills the ~30% LSU duty-cycle bubble measured
// in R4/R6 where DRAM% tracked latency/(latency+compute) ~= 70%).
//
// Per iteration (row r, stride nwarp):
//   [A holds first half of row r, loaded last iteration]
//   issue  B <- second half of row r
//   process A
//   issue  A <- first half of row r+nwarp   (overlaps with B in flight)
//   process B
//   butterfly-reduce + store row r          (A for next row still in flight)
//
// lane = 4q + c. Half h, step j: float4 (4h+j)*32 + lane lies in
// f = 8*(4h+j)+q, e-quarter c. Quad butterfly (xor 1,2) completes the e-sum;
// 3 accumulators own p in {c, c+4, c+8} (p>=10 zero-padded); xor 4,8,16
// sums over q-groups; lanes 0..9 store out[r*10+lane].

#define R_ROWS 32768
#define F_DIM 64
#define E_DIM 16
#define P_DIM 10
#define P_PAD 12
#define THREADS 256
#define BLOCKS 592   // 4 blocks/SM * 148 SMs, single wave; grid-stride rows

__global__ __launch_bounds__(THREADS, 4) void ip_fused_kernel(
    const float* __restrict__ x,
    const float* __restrict__ w,
    float* __restrict__ out)
{
    // [f][12] layout: word addr = f*12 + p. Access (8j+q)*12 + 4t + c:
    // banks (12q+c) mod 32 all distinct across the warp -> conflict-free.
    __shared__ float sh_wsq[F_DIM * P_PAD];

    for (int i = threadIdx.x; i < F_DIM * P_PAD; i += THREADS) {
        const int f = i / P_PAD;
        const int p = i - f * P_PAD;
        float v = (p < P_DIM) ? w[p * F_DIM + f] : 0.0f;
        sh_wsq[i] = v * v;
    }
    __syncthreads();

    const int lane = threadIdx.x & 31;
    const int q = lane >> 2;
    const int c = lane & 3;
    const int warp = threadIdx.x >> 5;
    const int gwarp = blockIdx.x * (THREADS / 32) + warp;
    const int nwarp = BLOCKS * (THREADS / 32);

    int r = gwarp;
    if (r >= R_ROWS) return;

    const float4* xr =
        reinterpret_cast<const float4*>(x + (size_t)r * (F_DIM * E_DIM));

    float4 A0, A1, A2, A3;   // first half of current row (prefetched)
    A0 = __ldcs(&xr[0 * 32 + lane]);
    A1 = __ldcs(&xr[1 * 32 + lane]);
    A2 = __ldcs(&xr[2 * 32 + lane]);
    A3 = __ldcs(&xr[3 * 32 + lane]);

    while (true) {
        // issue second half of row r
        float4 B0 = __ldcs(&xr[4 * 32 + lane]);
        float4 B1 = __ldcs(&xr[5 * 32 + lane]);
        float4 B2 = __ldcs(&xr[6 * 32 + lane]);
        float4 B3 = __ldcs(&xr[7 * 32 + lane]);

        float acc0 = 0.0f, acc1 = 0.0f, acc2 = 0.0f;

        // process first half (j = 0..3)
#pragma unroll
        for (int j = 0; j < 4; ++j) {
            float4 a = (j == 0) ? A0 : (j == 1) ? A1 : (j == 2) ? A2 : A3;
            float s = fmaf(a.x, a.x,
                      fmaf(a.y, a.y,
                      fmaf(a.z, a.z, a.w * a.w)));
            s += __shfl_xor_sync(0xFFFFFFFFu, s, 1);
            s += __shfl_xor_sync(0xFFFFFFFFu, s, 2);
            const float* wrow = &sh_wsq[(8 * j + q) * P_PAD + c];
            acc0 = fmaf(wrow[0], s, acc0);
            acc1 = fmaf(wrow[4], s, acc1);
            acc2 = fmaf(wrow[8], s, acc2);
        }

        // issue first half of the NEXT row (clamped address if past end;
        // the redundant read keeps the pipeline branch-free)
        const int rn = r + nwarp;
        const bool more = (rn < R_ROWS);
        const float4* xn = more
            ? reinterpret_cast<const float4*>(x + (size_t)rn * (F_DIM * E_DIM))
            : xr;
        A0 = __ldcs(&xn[0 * 32 + lane]);
        A1 = __ldcs(&xn[1 * 32 + lane]);
        A2 = __ldcs(&xn[2 * 32 + lane]);
        A3 = __ldcs(&xn[3 * 32 + lane]);

        // process second half (j = 4..7)
#pragma unroll
        for (int j = 0; j < 4; ++j) {
            float4 a = (j == 0) ? B0 : (j == 1) ? B1 : (j == 2) ? B2 : B3;
            float s = fmaf(a.x, a.x,
                      fmaf(a.y, a.y,
                      fmaf(a.z, a.z, a.w * a.w)));
            s += __shfl_xor_sync(0xFFFFFFFFu, s, 1);
            s += __shfl_xor_sync(0xFFFFFFFFu, s, 2);
            const float* wrow = &sh_wsq[(8 * (j + 4) + q) * P_PAD + c];
            acc0 = fmaf(wrow[0], s, acc0);
            acc1 = fmaf(wrow[4], s, acc1);
            acc2 = fmaf(wrow[8], s, acc2);
        }

        // reduce across the 8 quads (sum over f-groups); c preserved
#pragma unroll
        for (int m = 4; m <= 16; m <<= 1) {
            acc0 += __shfl_xor_sync(0xFFFFFFFFu, acc0, m);
            acc1 += __shfl_xor_sync(0xFFFFFFFFu, acc1, m);
            acc2 += __shfl_xor_sync(0xFFFFFFFFu, acc2, m);
        }

        if (lane < P_DIM) {
            float res = (lane < 4) ? acc0 : (lane < 8) ? acc1 : acc2;
            out[(size_t)r * P_DIM + lane] = res;
        }

        if (!more) break;
        r = rn;
        xr = xn;
    }
}

extern "C" void kernel_launch(void* const* d_in, const int* in_sizes, int n_in,
                              void* d_out, int out_size)
{
    const float* x = (const float*)d_in[0];   // [32768, 64, 16]
    const float* w = (const float*)d_in[1];   // [10, 64]
    float* out = (float*)d_out;               // [32768, 10]
    (void)in_sizes; (void)n_in; (void)out_size;

    ip_fused_kernel<<<BLOCKS, THREADS>>>(x, w, out);
}

// round 8
// speedup vs baseline: 1.0200x; 1.0200x over previous
#include <cuda_runtime.h>

// lp[r,p] = sum_f w[p,f]^2 * sum_e x[r,f,e]^2
// x: [R=32768, F=64, E=16] fp32 (row = 1024 floats = 4KB contiguous)
// w: [P=10, F=64] fp32 ; out: [R, 10] fp32
//
// Warp-per-row with FULL-ROW double buffering: all 8 loads of the NEXT row
// are issued before processing the current row, so the warp's LSU stream has
// no bubble during the shfl/FMA/store tail (R4/R6 measured DRAM% pinned at
// ~ latency/(latency+tail) ~= 70%, invariant to occupancy -> duty-cycle
// limited, not occupancy limited).
//
// __launch_bounds__(256,3) -> 85-reg budget so the 16 live float4s never
// force ptxas to sink the prefetch loads (the R7 failure mode at 64 regs).
//
// lane = 4q + c. Step j: float4 j*32+lane lies in f = 8j+q, e-quarter c.
// Quad butterfly (xor 1,2) completes the e-sum; 3 accumulators per lane own
// p in {c, c+4, c+8} (p>=10 zero-padded); xor 4,8,16 sums over q-groups;
// lanes 0..9 store out[r*10+lane].

#define R_ROWS 32768
#define F_DIM 64
#define E_DIM 16
#define P_DIM 10
#define P_PAD 12
#define THREADS 256
#define BLOCKS 444   // 3 blocks/SM * 148 SMs, single wave; grid-stride rows

__global__ __launch_bounds__(THREADS, 3) void ip_fused_kernel(
    const float* __restrict__ x,
    const float* __restrict__ w,
    float* __restrict__ out)
{
    // [f][12] layout: word addr = f*12 + p. Access (8j+q)*12 + 4t + c:
    // banks (12q+c) mod 32 all distinct across the warp -> conflict-free.
    __shared__ float sh_wsq[F_DIM * P_PAD];

    for (int i = threadIdx.x; i < F_DIM * P_PAD; i += THREADS) {
        const int f = i / P_PAD;
        const int p = i - f * P_PAD;
        float v = (p < P_DIM) ? w[p * F_DIM + f] : 0.0f;
        sh_wsq[i] = v * v;
    }
    __syncthreads();

    const int lane = threadIdx.x & 31;
    const int q = lane >> 2;
    const int c = lane & 3;
    const int warp = threadIdx.x >> 5;
    const int gwarp = blockIdx.x * (THREADS / 32) + warp;
    const int nwarp = BLOCKS * (THREADS / 32);

    int r = gwarp;
    if (r >= R_ROWS) return;

    const float4* xr =
        reinterpret_cast<const float4*>(x + (size_t)r * (F_DIM * E_DIM));

    // Prologue: load row r entirely (8-deep MLP).
    float4 V[8];
#pragma unroll
    for (int j = 0; j < 8; ++j) {
        V[j] = __ldcs(&xr[j * 32 + lane]);
    }

    while (true) {
        // Issue ALL loads for the next row before touching V. Past the end,
        // re-read the current row (harmless, keeps the loop branch-free).
        const int rn = r + nwarp;
        const bool more = (rn < R_ROWS);
        const float4* xn = reinterpret_cast<const float4*>(
            x + (size_t)(more ? rn : r) * (F_DIM * E_DIM));

        float4 W[8];
#pragma unroll
        for (int j = 0; j < 8; ++j) {
            W[j] = __ldcs(&xn[j * 32 + lane]);
        }

        // Process row r from V while W is in flight.
        float acc0 = 0.0f, acc1 = 0.0f, acc2 = 0.0f;
#pragma unroll
        for (int j = 0; j < 8; ++j) {
            float4 a = V[j];
            float s = fmaf(a.x, a.x,
                      fmaf(a.y, a.y,
                      fmaf(a.z, a.z, a.w * a.w)));
            // complete the e-sum (16 values span the quad)
            s += __shfl_xor_sync(0xFFFFFFFFu, s, 1);
            s += __shfl_xor_sync(0xFFFFFFFFu, s, 2);
            const float* wrow = &sh_wsq[(8 * j + q) * P_PAD + c];
            acc0 = fmaf(wrow[0], s, acc0);
            acc1 = fmaf(wrow[4], s, acc1);
            acc2 = fmaf(wrow[8], s, acc2);
        }

        // reduce across the 8 quads (sum over f-groups); c preserved
#pragma unroll
        for (int m = 4; m <= 16; m <<= 1) {
            acc0 += __shfl_xor_sync(0xFFFFFFFFu, acc0, m);
            acc1 += __shfl_xor_sync(0xFFFFFFFFu, acc1, m);
            acc2 += __shfl_xor_sync(0xFFFFFFFFu, acc2, m);
        }

        if (lane < P_DIM) {
            float res = (lane < 4) ? acc0 : (lane < 8) ? acc1 : acc2;
            out[(size_t)r * P_DIM + lane] = res;
        }

        if (!more) break;
        r = rn;
        xr = xn;
#pragma unroll
        for (int j = 0; j < 8; ++j) {
            V[j] = W[j];
        }
    }
}

extern "C" void kernel_launch(void* const* d_in, const int* in_sizes, int n_in,
                              void* d_out, int out_size)
{
    const float* x = (const float*)d_in[0];   // [32768, 64, 16]
    const float* w = (const float*)d_in[1];   // [10, 64]
    float* out = (float*)d_out;               // [32768, 10]
    (void)in_sizes; (void)n_in; (void)out_size;

    ip_fused_kernel<<<BLOCKS, THREADS>>>(x, w, out);
}